// round 17
// baseline (speedup 1.0000x reference)
#include <cuda_runtime.h>

#define BS 8
#define LQ 2049
#define NC 32
#define NH 16
#define KS 5
#define NL 4
#define NPOS (BS*LQ)            // 16392
#define TILE 16
#define NTILE 1025              // ceil(NPOS/16)
#define KA 584                  // 512 Gsum + 32 fsum + 32 enc + 1 one + 7 pad
#define KQ (KA/4)               // 146
#define AST 18                  // column-major A stride (floats)
#define NSEG 8
#define SEGW 129                // tiles per stats segment (8*129 >= 1025)

#define BUILD_BLOCKS 2049       // NPOS*NC/256
#define MLPB 321                // per-layer MLP blocks
#define WC_BLOCKS 292           // NL*KA*32/256
#define PREP_BLOCKS (BUILD_BLOCKS + NL*MLPB + WC_BLOCKS)

// -------- device scratch --------
__device__ __align__(16) float g_times[BS*LQ];
__device__ __align__(16) float g_enc[NPOS*NC];
__device__ __align__(16) float g_raw[2][NTILE*TILE*NC];   // ping-pong
__device__ __align__(16) float g_H2[NL*NPOS*KS*NH];       // 21 MB, all layers
__device__ __align__(16) float g_Wd[NL*KA*64];            // duplicated W pairs, 598 KB
__device__ __align__(16) float g_psum[NTILE*NC];
__device__ __align__(16) float g_psq[NTILE*NC];
__device__ __align__(16) float g_fs8[NSEG*NC];
__device__ __align__(16) float g_fs28[NSEG*NC];
__device__ int g_maxtype;

__device__ __forceinline__ float lrelu(float x) { return x >= 0.f ? x : 0.1f*x; }

__device__ __forceinline__ void fma2(unsigned long long& acc,
                                     unsigned long long a, unsigned long long w) {
    asm("fma.rn.f32x2 %0, %1, %2, %0;" : "+l"(acc) : "l"(a), "l"(w));
}
__device__ __forceinline__ unsigned long long add2(unsigned long long a,
                                                   unsigned long long b) {
    unsigned long long r;
    asm("add.rn.f32x2 %0, %1, %2;" : "=l"(r) : "l"(a), "l"(b));
    return r;
}
__device__ __forceinline__ float lo32(unsigned long long a) {
    float x, y; asm("mov.b64 {%0, %1}, %2;" : "=f"(x), "=f"(y) : "l"(a)); return x;
}
__device__ __forceinline__ float hi32(unsigned long long a) {
    float x, y; asm("mov.b64 {%0, %1}, %2;" : "=f"(x), "=f"(y) : "l"(a)); return y;
}

// -------- prep 1: max type, times --------
__global__ void k_max(const float* __restrict__ et, const int* __restrict__ types) {
    __shared__ int sm[1024];
    int t = threadIdx.x, m = 0;
    for (int i = t; i < BS*2048; i += 1024) m = max(m, types[i]);
    sm[t] = m;
    for (int s = 512; s > 0; s >>= 1) {
        __syncthreads();
        if (t < s) sm[t] = max(sm[t], sm[t+s]);
    }
    __syncthreads();
    if (t == 0) g_maxtype = sm[0];
    for (int i = t; i < NPOS; i += 1024) {
        int b = i / LQ, l = i - b*LQ;
        g_times[i] = (l == 0) ? 0.f : et[b*2048 + l - 1];
    }
}

// -------- prep 2 (merged): enc build | all-layer MLP | Wd build --------
__global__ __launch_bounds__(256) void k_prep(
        const int* __restrict__ ty, const float* __restrict__ emb,
        const float* __restrict__ k1W, const float* __restrict__ k1b,
        const float* __restrict__ k2W, const float* __restrict__ k2b,
        const float* __restrict__ k3W, const float* __restrict__ k3b,
        const float* __restrict__ skipW, const float* __restrict__ skipb) {
    int bid = blockIdx.x;
    int t = threadIdx.x;

    if (bid < BUILD_BLOCKS) {
        int idx = bid*256 + t;
        if (idx >= NPOS*NC) return;
        int pos = idx >> 5, c = idx & 31;
        int b = pos / LQ, l = pos - b*LQ;
        int tp = (l == 0) ? (g_maxtype + 1) : ty[b*2048 + l - 1];
        g_enc[idx] = (tp == 0) ? 0.f : emb[tp*NC + c];
        return;
    }
    if (bid < BUILD_BLOCKS + NL*MLPB) {
        int idx2 = bid - BUILD_BLOCKS;
        int layer = idx2 / MLPB;
        int blk = idx2 - layer*MLPB;
        int dil = 1 << layer;
        __shared__ float sk1[NH], sk1b[NH], sk2[NH*NH], sk2b[NH];
        if (t < NH) { sk1[t] = k1W[layer*NH + t]; sk1b[t] = k1b[layer*NH + t];
                      sk2b[t] = k2b[layer*NH + t]; }
        sk2[t] = k2W[layer*NH*NH + t];
        __syncthreads();
        int idx = blk*256 + t;
        if (idx >= NPOS*KS) return;
        int pos = idx / KS, k = idx - pos*KS;
        int b = pos / LQ, l = pos - b*LQ;
        float out[NH];
        bool valid = false;
        int j = l - k*dil;
        float tl = g_times[pos];
        if (j >= 0 && tl != 0.f) {
            float tj = g_times[b*LQ + j];
            if (tj != 0.f) {
                valid = true;
                float dt = tl - tj;
                float h1[NH];
                #pragma unroll
                for (int h = 0; h < NH; h++) h1[h] = lrelu(fmaf(dt, sk1[h], sk1b[h]));
                #pragma unroll
                for (int hh = 0; hh < NH; hh++) {
                    float s = sk2b[hh];
                    #pragma unroll
                    for (int x = 0; x < NH; x++) s = fmaf(h1[x], sk2[x*NH + hh], s);
                    out[hh] = lrelu(s);
                }
            }
        }
        if (!valid) {
            #pragma unroll
            for (int h = 0; h < NH; h++) out[h] = 0.f;
        }
        float* dst = g_H2 + (size_t)((layer*NPOS + pos)*KS + k)*NH;
        #pragma unroll
        for (int q = 0; q < 4; q++)
            *reinterpret_cast<float4*>(dst + 4*q) =
                make_float4(out[4*q], out[4*q+1], out[4*q+2], out[4*q+3]);
        return;
    }
    {
        int idx = (bid - BUILD_BLOCKS - NL*MLPB)*256 + t;
        if (idx >= NL*KA*32) return;
        int layer = idx / (KA*32);
        int rem = idx - layer*(KA*32);
        int r = rem >> 5, d = rem & 31;
        float v;
        if (r < 512)      v = k3W[layer*16384 + r*32 + d];
        else if (r < 544) v = k3b[layer*1024 + (r-512)*32 + d];
        else if (r < 576) v = skipW[layer*1024 + (r-544)*32 + d];
        else if (r == 576) v = skipb[layer*32 + d];
        else v = 0.f;
        float* p = g_Wd + ((size_t)(layer*KA + r)*32 + d)*2;
        p[0] = v; p[1] = v;
    }
}

// -------- fused: phase A (col-major smem A) + position-paired f32x2 GEMM ----
__global__ __launch_bounds__(256) void k_fused(int layer, int dil, int first,
        const float* __restrict__ gamma, const float* __restrict__ beta) {
    __shared__ float s_bn[64];
    __shared__ __align__(16) float s_A[KA*AST];           // 42048 B, A^T[k][p]
    __shared__ __align__(16) float s_ps[TILE*NC], s_ps2[TILE*NC];
    __shared__ __align__(16) float s_red[TILE*NC];
    int t = threadIdx.x;
    int lane = t & 31, warp = t >> 5;
    int tile = blockIdx.x;
    const float* raw_in = g_raw[(layer + 1) & 1];
    float* raw_out = g_raw[layer & 1];

    if (!first && t < 32) {
        float fsv = 0.f, fs2v = 0.f;
        #pragma unroll
        for (int s = 0; s < NSEG; s++) { fsv += g_fs8[s*32 + t]; fs2v += g_fs28[s*32 + t]; }
        float inv = 1.0f / (float)NPOS;
        float mu = fsv * inv;
        float var = fs2v * inv - mu*mu;
        float scale = rsqrtf(var + 1e-5f) * gamma[(layer-1)*32 + t];
        s_bn[t]      = scale;
        s_bn[32 + t] = beta[(layer-1)*32 + t] - mu*scale;
    }
    __syncthreads();

    // ---- phase A: 8 warps x 2 positions; lane = channel c; col-major store --
    #pragma unroll
    for (int wp = 0; wp < 2; wp++) {
        int p = warp*2 + wp;
        int pos = tile*TILE + p;
        float G[NH];
        #pragma unroll
        for (int h = 0; h < NH; h++) G[h] = 0.f;
        float fs = 0.f, en = 0.f, one = 0.f;
        if (pos < NPOS) {
            one = 1.f;
            int b = pos / LQ, l = pos - b*LQ;
            float tl = g_times[pos];
            if (first) en = g_enc[pos*NC + lane];
            else {
                float v = fmaf(raw_in[pos*NC + lane], s_bn[lane], s_bn[32 + lane]);
                en = v >= 0.f ? v : 0.1f*v;
            }
            if (tl != 0.f) {
                const float* h2p = g_H2 + (size_t)((layer*NPOS + pos)*KS)*NH;
                for (int k = 0; k < KS; k++) {
                    int j = l - k*dil;
                    if (j < 0) break;
                    float tj = g_times[b*LQ + j];
                    if (tj != 0.f) {
                        int pj = pos - k*dil;
                        float g;
                        if (first) g = g_enc[pj*NC + lane];
                        else {
                            float v = fmaf(raw_in[pj*NC + lane], s_bn[lane], s_bn[32 + lane]);
                            g = v >= 0.f ? v : 0.1f*v;
                        }
                        fs += g;
                        float4 h0 = *reinterpret_cast<const float4*>(h2p + k*NH + 0);
                        float4 h1 = *reinterpret_cast<const float4*>(h2p + k*NH + 4);
                        float4 h2 = *reinterpret_cast<const float4*>(h2p + k*NH + 8);
                        float4 h3 = *reinterpret_cast<const float4*>(h2p + k*NH + 12);
                        G[0]  = fmaf(h0.x, g, G[0]);   G[1]  = fmaf(h0.y, g, G[1]);
                        G[2]  = fmaf(h0.z, g, G[2]);   G[3]  = fmaf(h0.w, g, G[3]);
                        G[4]  = fmaf(h1.x, g, G[4]);   G[5]  = fmaf(h1.y, g, G[5]);
                        G[6]  = fmaf(h1.z, g, G[6]);   G[7]  = fmaf(h1.w, g, G[7]);
                        G[8]  = fmaf(h2.x, g, G[8]);   G[9]  = fmaf(h2.y, g, G[9]);
                        G[10] = fmaf(h2.z, g, G[10]);  G[11] = fmaf(h2.w, g, G[11]);
                        G[12] = fmaf(h3.x, g, G[12]);  G[13] = fmaf(h3.y, g, G[13]);
                        G[14] = fmaf(h3.z, g, G[14]);  G[15] = fmaf(h3.w, g, G[15]);
                    }
                }
            }
        }
        #pragma unroll
        for (int h = 0; h < NH; h++) s_A[(h*32 + lane)*AST + p] = G[h];
        s_A[(512 + lane)*AST + p] = fs;
        s_A[(544 + lane)*AST + p] = en;
        if (lane == 0) s_A[576*AST + p] = one;
        if (lane < 7)  s_A[(577 + lane)*AST + p] = 0.f;
    }
    __syncthreads();

    // ---- GEMM: position-paired f32x2, 4-way K-split, duplicated W ----
    int tx = t & 7;            // d0 = 4*tx
    int pp = (t >> 3) & 7;     // positions 2*pp, 2*pp+1
    int ks = t >> 6;           // 0..3
    const float* Ap = s_A + (ks*KQ)*AST + 2*pp;
    const float* Wl = g_Wd + ((size_t)(layer*KA + ks*KQ)*32 + 4*tx)*2;
    unsigned long long a0 = 0ULL, a1 = 0ULL, a2 = 0ULL, a3 = 0ULL; // (p0,p1) per d
    #pragma unroll 4
    for (int k = 0; k < KQ; k++) {
        unsigned long long ap = *reinterpret_cast<const unsigned long long*>(Ap + k*AST);
        ulonglong2 w0 = *reinterpret_cast<const ulonglong2*>(Wl + k*64);
        ulonglong2 w1 = *reinterpret_cast<const ulonglong2*>(Wl + k*64 + 4);
        fma2(a0, ap, w0.x); fma2(a1, ap, w0.y);
        fma2(a2, ap, w1.x); fma2(a3, ap, w1.y);
    }

    // ---- combine K-split partials (fixed order: ks0+ks1+ks2+ks3) ----
    unsigned long long* sb1 = reinterpret_cast<unsigned long long*>(s_ps);
    unsigned long long* sb2 = reinterpret_cast<unsigned long long*>(s_ps2);
    unsigned long long* sb3 = reinterpret_cast<unsigned long long*>(s_red);
    int g = t & 63;            // pp*8 + tx
    if (ks == 1)      { sb1[g*4+0]=a0; sb1[g*4+1]=a1; sb1[g*4+2]=a2; sb1[g*4+3]=a3; }
    else if (ks == 2) { sb2[g*4+0]=a0; sb2[g*4+1]=a1; sb2[g*4+2]=a2; sb2[g*4+3]=a3; }
    else if (ks == 3) { sb3[g*4+0]=a0; sb3[g*4+1]=a1; sb3[g*4+2]=a2; sb3[g*4+3]=a3; }
    __syncthreads();
    unsigned long long f0 = add2(add2(add2(a0, sb1[g*4+0]), sb2[g*4+0]), sb3[g*4+0]);
    unsigned long long f1 = add2(add2(add2(a1, sb1[g*4+1]), sb2[g*4+1]), sb3[g*4+1]);
    unsigned long long f2 = add2(add2(add2(a2, sb1[g*4+2]), sb2[g*4+2]), sb3[g*4+2]);
    unsigned long long f3 = add2(add2(add2(a3, sb1[g*4+3]), sb2[g*4+3]), sb3[g*4+3]);
    __syncthreads();           // staging reads done before s_ps reuse
    if (ks == 0) {
        int p0 = 2*pp, p1 = 2*pp + 1;
        float4 rp0 = make_float4(lo32(f0), lo32(f1), lo32(f2), lo32(f3));
        float4 rp1 = make_float4(hi32(f0), hi32(f1), hi32(f2), hi32(f3));
        *reinterpret_cast<float4*>(raw_out + (size_t)(tile*TILE + p0)*NC + 4*tx) = rp0;
        *reinterpret_cast<float4*>(raw_out + (size_t)(tile*TILE + p1)*NC + 4*tx) = rp1;
        *reinterpret_cast<float4*>(&s_ps [p0*32 + 4*tx]) = rp0;
        *reinterpret_cast<float4*>(&s_ps [p1*32 + 4*tx]) = rp1;
        *reinterpret_cast<float4*>(&s_ps2[p0*32 + 4*tx]) =
            make_float4(rp0.x*rp0.x, rp0.y*rp0.y, rp0.z*rp0.z, rp0.w*rp0.w);
        *reinterpret_cast<float4*>(&s_ps2[p1*32 + 4*tx]) =
            make_float4(rp1.x*rp1.x, rp1.y*rp1.y, rp1.z*rp1.z, rp1.w*rp1.w);
    }
    __syncthreads();
    if (t < 32) {
        float s = 0.f, s2 = 0.f;
        #pragma unroll
        for (int r = 0; r < TILE; r++) { s += s_ps[r*32 + t]; s2 += s_ps2[r*32 + t]; }
        g_psum[tile*32 + t] = s;
        g_psq [tile*32 + t] = s2;
    }
}

// -------- BN stats: (32 ch x 8 seg) blocks, fixed-tree reduction --------
__global__ __launch_bounds__(256) void k_statsA() {
    __shared__ float ss[256], ss2[256];
    int ch = blockIdx.x, seg = blockIdx.y;
    int t = threadIdx.x;
    float s = 0.f, s2 = 0.f;
    int b = seg*SEGW + t;
    if (t < SEGW && b < NTILE) { s = g_psum[b*32 + ch]; s2 = g_psq[b*32 + ch]; }
    ss[t] = s; ss2[t] = s2;
    for (int st = 128; st > 0; st >>= 1) {
        __syncthreads();
        if (t < st) { ss[t] += ss[t+st]; ss2[t] += ss2[t+st]; }
    }
    if (t == 0) { g_fs8[seg*32 + ch] = ss[0]; g_fs28[seg*32 + ch] = ss2[0]; }
}

// -------- final apply: BN (seg-reduced in preamble) + leaky ReLU -> output ---
__global__ void k_apply(float* dst, int buf,
                        const float* __restrict__ gamma, const float* __restrict__ beta) {
    __shared__ float s_bn[64];
    int t = threadIdx.x;
    if (t < 32) {
        float fsv = 0.f, fs2v = 0.f;
        #pragma unroll
        for (int s = 0; s < NSEG; s++) { fsv += g_fs8[s*32 + t]; fs2v += g_fs28[s*32 + t]; }
        float inv = 1.0f / (float)NPOS;
        float mu = fsv * inv;
        float var = fs2v * inv - mu*mu;
        float scale = rsqrtf(var + 1e-5f) * gamma[(NL-1)*32 + t];
        s_bn[t]      = scale;
        s_bn[32 + t] = beta[(NL-1)*32 + t] - mu*scale;
    }
    __syncthreads();
    int idx = blockIdx.x*blockDim.x + t;
    if (idx >= NPOS*NC) return;
    int n = idx & 31;
    float v = fmaf(g_raw[buf][idx], s_bn[n], s_bn[32 + n]);
    dst[idx] = v >= 0.f ? v : 0.1f*v;
}

extern "C" void kernel_launch(void* const* d_in, const int* in_sizes, int n_in,
                              void* d_out, int out_size) {
    const float* event_times = (const float*)d_in[0];
    const int*   event_types = (const int*)  d_in[1];
    const float* emb   = (const float*)d_in[2];
    const float* k1W   = (const float*)d_in[3];
    const float* k1b   = (const float*)d_in[4];
    const float* k2W   = (const float*)d_in[5];
    const float* k2b   = (const float*)d_in[6];
    const float* k3W   = (const float*)d_in[7];
    const float* k3b   = (const float*)d_in[8];
    const float* skipW = (const float*)d_in[9];
    const float* skipb = (const float*)d_in[10];
    const float* gamma = (const float*)d_in[11];
    const float* beta  = (const float*)d_in[12];
    float* out = (float*)d_out;

    k_max<<<1, 1024>>>(event_times, event_types);
    k_prep<<<PREP_BLOCKS, 256>>>(event_types, emb, k1W, k1b, k2W, k2b,
                                 k3W, k3b, skipW, skipb);

    const int dil[NL] = {1, 2, 4, 8};
    for (int i = 0; i < NL; i++) {
        k_fused<<<NTILE, 256>>>(i, dil[i], i == 0, gamma, beta);
        k_statsA<<<dim3(NC, NSEG), 256>>>();
    }
    k_apply<<<(NPOS*NC + 255)/256, 256>>>(out, (NL-1) & 1, gamma, beta);
}